// round 14
// baseline (speedup 1.0000x reference)
#include <cuda_runtime.h>
#include <cuda_bf16.h>
#include <cstdint>

// ---------------------------------------------------------------------------
// 2-layer GRU (H=32, INPUT=4, B=4096, S=512) + FC(32->32) + FC(32->1)
//
// SINGLE kernel, warp-specialized 3-stage pipeline per CTA (2 batch rows):
//   warp A : layer-1 recurrence (Whh0 in regs)      -> h1 smem ring
//   warp B : xg = W_ih1 . h1 GEMM (Wih1 in regs)    -> xg smem ring
//   warp C0/C1 : layer-2 recurrence row 0/1 (Whh1)  -> FC epilogue
// Chunked (8-step) named-barrier rendezvous; depth-2 rings; no gmem scratch.
// stage = (wid + blockIdx) & 3 rotates stages across SMSPs for balance.
// ---------------------------------------------------------------------------

#define B_ROWS 4096
#define SEQ    512
#define HID    32
#define CH     8
#define NCH    (SEQ / CH)

typedef unsigned long long ull;

__device__ __forceinline__ ull ffma2(ull a, ull b, ull c) {
    ull d;
    asm("fma.rn.f32x2 %0, %1, %2, %3;" : "=l"(d) : "l"(a), "l"(b), "l"(c));
    return d;
}
__device__ __forceinline__ float hsum2(ull v) {
    float2 r;
    asm("mov.b64 {%0, %1}, %2;" : "=f"(r.x), "=f"(r.y) : "l"(v));
    return r.x + r.y;
}
__device__ __forceinline__ float tanh_ap(float x) {
    float y;
    asm("tanh.approx.f32 %0, %1;" : "=f"(y) : "f"(x));
    return y;
}
__device__ __forceinline__ float sig_ap(float x) {
    return fmaf(0.5f, tanh_ap(0.5f * x), 0.5f);
}
__device__ __forceinline__ void cp_async16(uint32_t smem_addr, const float* gptr) {
    asm volatile("cp.async.ca.shared.global [%0], [%1], 16;"
                 :: "r"(smem_addr), "l"(gptr));
}
__device__ __forceinline__ void cp_commit() {
    asm volatile("cp.async.commit_group;");
}
__device__ __forceinline__ void cp_wait_1() {
    asm volatile("cp.async.wait_group 1;");
}
#define BAR_SYNC(id, cnt) \
    asm volatile("bar.sync %0, %1;" :: "r"(id), "r"(cnt) : "memory")

__global__ __launch_bounds__(128, 3)
void gru_pipeline_kernel(const float* __restrict__ x,
                         const float* __restrict__ Wih0,  // [96,4]
                         const float* __restrict__ Whh0,  // [96,32]
                         const float* __restrict__ bih0,  // [96]
                         const float* __restrict__ bhh0,  // [96]
                         const float* __restrict__ Wih1,  // [96,32]
                         const float* __restrict__ Whh1,  // [96,32]
                         const float* __restrict__ bih1,  // [96]
                         const float* __restrict__ bhh1,  // [96]
                         const float* __restrict__ Wfc2,  // [32,32]
                         const float* __restrict__ bfc2,  // [32]
                         const float* __restrict__ Wfc,   // [1,32]
                         const float* __restrict__ bfc,   // [1]
                         float* __restrict__ out)
{
    __shared__ __align__(16) float h1ring[2][CH][2][HID];   // 4 KB
    __shared__ __align__(16) float xgring[2][CH][2][96];    // 12 KB
    __shared__ __align__(16) float xc[2][2][CH][4];         // 512 B
    __shared__ __align__(16) float hcb[2][2][HID];          // 512 B

    const int bid   = blockIdx.x;
    const int wid   = threadIdx.x >> 5;
    const int lane  = threadIdx.x & 31;
    const int stage = (wid + bid) & 3;

    if (stage == 0) {
        // ================= A: layer-1 recurrence, 2 rows ===================
        ull whr[16], whz[16], whn[16];
        {
            const ull* pr = reinterpret_cast<const ull*>(Whh0 + (lane)      * HID);
            const ull* pz = reinterpret_cast<const ull*>(Whh0 + (32 + lane) * HID);
            const ull* pn = reinterpret_cast<const ull*>(Whh0 + (64 + lane) * HID);
#pragma unroll
            for (int k = 0; k < 16; k++) { whr[k] = pr[k]; whz[k] = pz[k]; whn[k] = pn[k]; }
        }
        const float4 wir = reinterpret_cast<const float4*>(Wih0)[lane];
        const float4 wiz = reinterpret_cast<const float4*>(Wih0)[32 + lane];
        const float4 win = reinterpret_cast<const float4*>(Wih0)[64 + lane];
        const float br  = bih0[lane]      + bhh0[lane];
        const float bz  = bih0[32 + lane] + bhh0[32 + lane];
        const float bin = bih0[64 + lane];
        const float bhn = bhh0[64 + lane];

        const float* xs0 = x + (size_t)(bid * 2) * SEQ * 4;
        const float* xs1 = xs0 + SEQ * 4;
        const uint32_t xcb =
            (uint32_t)__cvta_generic_to_shared(&xc[0][0][0][0]);

        // bootstrap zero slot (read at c=0,t=0)
        h1ring[1][CH - 1][0][lane] = 0.0f;
        h1ring[1][CH - 1][1][lane] = 0.0f;
        __syncwarp();

        const int   lrow = lane >> 3;
        const int   lq   = lane & 7;
        const float* lsrc = lrow ? xs1 : xs0;

#pragma unroll
        for (int d = 0; d < 2; d++) {
            if (lane < 16)
                cp_async16(xcb + d * 256 + lrow * 128 + lq * 16,
                           lsrc + d * CH * 4 + lq * 4);
            cp_commit();
        }

        float h0 = 0.0f, h1v = 0.0f;
#pragma unroll 1
        for (int c = 0; c < NCH; c++) {
            cp_wait_1();
            __syncwarp();
            if (lane < 16 && c + 2 < NCH)
                cp_async16(xcb + ((c + 2) & 1) * 256 + lrow * 128 + lq * 16,
                           lsrc + (c + 2) * CH * 4 + lq * 4);
            cp_commit();

            const int cb = c & 1;
            const int pbAlt = cb ^ 1;
#pragma unroll
            for (int t = 0; t < CH; t++) {
                const int pb = (t == 0) ? pbAlt : cb;
                const int pt = (t == 0) ? CH - 1 : t - 1;
                const ulonglong2* hp0 =
                    reinterpret_cast<const ulonglong2*>(&h1ring[pb][pt][0][0]);
                const ulonglong2* hp1 =
                    reinterpret_cast<const ulonglong2*>(&h1ring[pb][pt][1][0]);
                const float4 xv0 = *reinterpret_cast<const float4*>(&xc[cb][0][t][0]);
                const float4 xv1 = *reinterpret_cast<const float4*>(&xc[cb][1][t][0]);

                float ar0 = br, az0 = bz, xn0 = bin;
                float ar1 = br, az1 = bz, xn1 = bin;
                ar0 = fmaf(wir.x, xv0.x, ar0); ar0 = fmaf(wir.y, xv0.y, ar0);
                ar0 = fmaf(wir.z, xv0.z, ar0); ar0 = fmaf(wir.w, xv0.w, ar0);
                az0 = fmaf(wiz.x, xv0.x, az0); az0 = fmaf(wiz.y, xv0.y, az0);
                az0 = fmaf(wiz.z, xv0.z, az0); az0 = fmaf(wiz.w, xv0.w, az0);
                xn0 = fmaf(win.x, xv0.x, xn0); xn0 = fmaf(win.y, xv0.y, xn0);
                xn0 = fmaf(win.z, xv0.z, xn0); xn0 = fmaf(win.w, xv0.w, xn0);
                ar1 = fmaf(wir.x, xv1.x, ar1); ar1 = fmaf(wir.y, xv1.y, ar1);
                ar1 = fmaf(wir.z, xv1.z, ar1); ar1 = fmaf(wir.w, xv1.w, ar1);
                az1 = fmaf(wiz.x, xv1.x, az1); az1 = fmaf(wiz.y, xv1.y, az1);
                az1 = fmaf(wiz.z, xv1.z, az1); az1 = fmaf(wiz.w, xv1.w, az1);
                xn1 = fmaf(win.x, xv1.x, xn1); xn1 = fmaf(win.y, xv1.y, xn1);
                xn1 = fmaf(win.z, xv1.z, xn1); xn1 = fmaf(win.w, xv1.w, xn1);

                ull ra0 = 0ull, za0 = 0ull, na0 = 0ull;
                ull ra1 = 0ull, za1 = 0ull, na1 = 0ull;
#pragma unroll
                for (int k = 0; k < 8; k++) {
                    const ulonglong2 hv0 = hp0[k];
                    const ulonglong2 hv1 = hp1[k];
                    ra0 = ffma2(whr[2 * k],     hv0.x, ra0);
                    za0 = ffma2(whz[2 * k],     hv0.x, za0);
                    na0 = ffma2(whn[2 * k],     hv0.x, na0);
                    ra1 = ffma2(whr[2 * k],     hv1.x, ra1);
                    za1 = ffma2(whz[2 * k],     hv1.x, za1);
                    na1 = ffma2(whn[2 * k],     hv1.x, na1);
                    ra0 = ffma2(whr[2 * k + 1], hv0.y, ra0);
                    za0 = ffma2(whz[2 * k + 1], hv0.y, za0);
                    na0 = ffma2(whn[2 * k + 1], hv0.y, na0);
                    ra1 = ffma2(whr[2 * k + 1], hv1.y, ra1);
                    za1 = ffma2(whz[2 * k + 1], hv1.y, za1);
                    na1 = ffma2(whn[2 * k + 1], hv1.y, na1);
                }
                ar0 += hsum2(ra0);  az0 += hsum2(za0);
                ar1 += hsum2(ra1);  az1 += hsum2(za1);
                const float hn0 = bhn + hsum2(na0);
                const float hn1 = bhn + hsum2(na1);

                const float rr0 = sig_ap(ar0);
                const float zz0 = sig_ap(az0);
                const float nn0 = tanh_ap(fmaf(rr0, hn0, xn0));
                h0 = fmaf(zz0, h0 - nn0, nn0);
                const float rr1 = sig_ap(ar1);
                const float zz1 = sig_ap(az1);
                const float nn1 = tanh_ap(fmaf(rr1, hn1, xn1));
                h1v = fmaf(zz1, h1v - nn1, nn1);

                h1ring[cb][t][0][lane] = h0;
                h1ring[cb][t][1][lane] = h1v;
                __syncwarp();
            }
            BAR_SYNC(1, 64);     // rendezvous with B: chunk c ready
        }
    } else if (stage == 1) {
        // ================= B: xg GEMM on h1 ring ===========================
        ull wxr[16], wxz[16], wxn[16];
        {
            const ull* p0 = reinterpret_cast<const ull*>(Wih1 + (lane)      * HID);
            const ull* p1 = reinterpret_cast<const ull*>(Wih1 + (32 + lane) * HID);
            const ull* p2 = reinterpret_cast<const ull*>(Wih1 + (64 + lane) * HID);
#pragma unroll
            for (int k = 0; k < 16; k++) { wxr[k] = p0[k]; wxz[k] = p1[k]; wxn[k] = p2[k]; }
        }
        const float gxr = bih1[lane]      + bhh1[lane];
        const float gxz = bih1[32 + lane] + bhh1[32 + lane];
        const float gxn = bih1[64 + lane];

#pragma unroll 1
        for (int c = 0; c < NCH; c++) {
            BAR_SYNC(1, 64);     // h1 chunk c ready
            const int cb = c & 1;
#pragma unroll
            for (int t = 0; t < CH; t++) {
                const ulonglong2* hp0 =
                    reinterpret_cast<const ulonglong2*>(&h1ring[cb][t][0][0]);
                const ulonglong2* hp1 =
                    reinterpret_cast<const ulonglong2*>(&h1ring[cb][t][1][0]);
                ull qr0 = 0ull, qz0 = 0ull, qn0 = 0ull;
                ull qr1 = 0ull, qz1 = 0ull, qn1 = 0ull;
#pragma unroll
                for (int k = 0; k < 8; k++) {
                    const ulonglong2 hv0 = hp0[k];
                    const ulonglong2 hv1 = hp1[k];
                    qr0 = ffma2(wxr[2 * k],     hv0.x, qr0);
                    qz0 = ffma2(wxz[2 * k],     hv0.x, qz0);
                    qn0 = ffma2(wxn[2 * k],     hv0.x, qn0);
                    qr1 = ffma2(wxr[2 * k],     hv1.x, qr1);
                    qz1 = ffma2(wxz[2 * k],     hv1.x, qz1);
                    qn1 = ffma2(wxn[2 * k],     hv1.x, qn1);
                    qr0 = ffma2(wxr[2 * k + 1], hv0.y, qr0);
                    qz0 = ffma2(wxz[2 * k + 1], hv0.y, qz0);
                    qn0 = ffma2(wxn[2 * k + 1], hv0.y, qn0);
                    qr1 = ffma2(wxr[2 * k + 1], hv1.y, qr1);
                    qz1 = ffma2(wxz[2 * k + 1], hv1.y, qz1);
                    qn1 = ffma2(wxn[2 * k + 1], hv1.y, qn1);
                }
                xgring[cb][t][0][lane]      = gxr + hsum2(qr0);
                xgring[cb][t][0][32 + lane] = gxz + hsum2(qz0);
                xgring[cb][t][0][64 + lane] = gxn + hsum2(qn0);
                xgring[cb][t][1][lane]      = gxr + hsum2(qr1);
                xgring[cb][t][1][32 + lane] = gxz + hsum2(qz1);
                xgring[cb][t][1][64 + lane] = gxn + hsum2(qn1);
            }
            BAR_SYNC(2, 96);     // xg chunk c ready for C0/C1
        }
    } else {
        // ================= C0/C1: layer-2 recurrence + FC ==================
        const int row = stage - 2;
        ull whr[16], whz[16], whn[16];
        {
            const ull* p3 = reinterpret_cast<const ull*>(Whh1 + (lane)      * HID);
            const ull* p4 = reinterpret_cast<const ull*>(Whh1 + (32 + lane) * HID);
            const ull* p5 = reinterpret_cast<const ull*>(Whh1 + (64 + lane) * HID);
#pragma unroll
            for (int k = 0; k < 16; k++) { whr[k] = p3[k]; whz[k] = p4[k]; whn[k] = p5[k]; }
        }
        const float bhn = bhh1[64 + lane];

        float h2 = 0.0f;
#pragma unroll 1
        for (int c = 0; c < NCH; c++) {
            BAR_SYNC(2, 96);     // xg chunk c ready
            const int cb = c & 1;
#pragma unroll
            for (int t = 0; t < CH; t++) {
                hcb[row][t & 1][lane] = h2;
                __syncwarp();
                const ulonglong2* hp =
                    reinterpret_cast<const ulonglong2*>(&hcb[row][t & 1][0]);
                const float xr = xgring[cb][t][row][lane];
                const float xz = xgring[cb][t][row][32 + lane];
                const float xn = xgring[cb][t][row][64 + lane];

                ull r = 0ull, z = 0ull, n = 0ull;
#pragma unroll
                for (int k = 0; k < 8; k++) {
                    const ulonglong2 hv = hp[k];
                    r = ffma2(whr[2 * k],     hv.x, r);
                    z = ffma2(whz[2 * k],     hv.x, z);
                    n = ffma2(whn[2 * k],     hv.x, n);
                    r = ffma2(whr[2 * k + 1], hv.y, r);
                    z = ffma2(whz[2 * k + 1], hv.y, z);
                    n = ffma2(whn[2 * k + 1], hv.y, n);
                }
                const float ar = xr  + hsum2(r);
                const float az = xz  + hsum2(z);
                const float hn = bhn + hsum2(n);

                const float rr = sig_ap(ar);
                const float zz = sig_ap(az);
                const float nn = tanh_ap(fmaf(rr, hn, xn));
                h2 = fmaf(zz, h2 - nn, nn);
            }
        }

        // FC2 + FC epilogue (per row)
        hcb[row][0][lane] = h2;
        __syncwarp();
        const ulonglong2* hp =
            reinterpret_cast<const ulonglong2*>(&hcb[row][0][0]);
        const ull* wf = reinterpret_cast<const ull*>(Wfc2 + lane * HID);
        ull acc = 0ull;
#pragma unroll
        for (int k = 0; k < 8; k++) {
            const ulonglong2 hv = hp[k];
            acc = ffma2(wf[2 * k],     hv.x, acc);
            acc = ffma2(wf[2 * k + 1], hv.y, acc);
        }
        const float o = __ldg(bfc2 + lane) + hsum2(acc);

        float p = __ldg(Wfc + lane) * o;
#pragma unroll
        for (int off = 16; off > 0; off >>= 1)
            p += __shfl_xor_sync(0xffffffffu, p, off);
        if (lane == 0)
            out[bid * 2 + row] = p + __ldg(bfc);
    }
}

// ---------------------------------------------------------------------------
// Launch
// ---------------------------------------------------------------------------
extern "C" void kernel_launch(void* const* d_in, const int* in_sizes, int n_in,
                              void* d_out, int out_size)
{
    const float* x     = (const float*)d_in[0];
    const float* Wih0  = (const float*)d_in[1];
    const float* Whh0  = (const float*)d_in[2];
    const float* bih0  = (const float*)d_in[3];
    const float* bhh0  = (const float*)d_in[4];
    const float* Wih1  = (const float*)d_in[5];
    const float* Whh1  = (const float*)d_in[6];
    const float* bih1  = (const float*)d_in[7];
    const float* bhh1  = (const float*)d_in[8];
    const float* Wfc2  = (const float*)d_in[9];
    const float* bfc2  = (const float*)d_in[10];
    const float* Wfc   = (const float*)d_in[11];
    const float* bfc   = (const float*)d_in[12];
    float* out = (float*)d_out;

    const int threads = 128;              // 4 specialist warps, 2 rows per CTA
    const int blocks  = B_ROWS / 2;       // 2048 CTAs

    gru_pipeline_kernel<<<blocks, threads>>>(x, Wih0, Whh0, bih0, bhh0,
                                             Wih1, Whh1, bih1, bhh1,
                                             Wfc2, bfc2, Wfc, bfc, out);
}

// round 15
// speedup vs baseline: 1.1088x; 1.1088x over previous
#include <cuda_runtime.h>
#include <cuda_bf16.h>
#include <cstdint>

// ---------------------------------------------------------------------------
// 2-layer GRU (H=32, INPUT=4, B=4096, S=512) + FC(32->32) + FC(32->1)
//
// Three kernels, all sized for ONE residency wave:
//  K1: layer-1 recurrence, 3 rows/warp (1366 warps < 1776 capacity) -> h1
//  K2: xg = W_ih1 . h1 + biases, pipelined cp.async GEMM (16384 warp-tasks)
//  K3: slim layer-2 recurrence (h-side only, 96 weight regs), 3 rows/warp
//      + FC epilogue.
// Remainder row (4096 = 3*1365+1) handled by clamped duplicate compute.
// ---------------------------------------------------------------------------

#define B_ROWS 4096
#define SEQ    512
#define HID    32
#define RING   8
#define NW3    1366               // 3-row warps (ceil(4096/3))

typedef unsigned long long ull;

__device__ float g_h1[(size_t)B_ROWS * SEQ * HID];   // 268 MB
__device__ float g_xg[(size_t)B_ROWS * SEQ * 96];    // 805 MB

__device__ __forceinline__ ull ffma2(ull a, ull b, ull c) {
    ull d;
    asm("fma.rn.f32x2 %0, %1, %2, %3;" : "=l"(d) : "l"(a), "l"(b), "l"(c));
    return d;
}
__device__ __forceinline__ float hsum2(ull v) {
    float2 r;
    asm("mov.b64 {%0, %1}, %2;" : "=f"(r.x), "=f"(r.y) : "l"(v));
    return r.x + r.y;
}
__device__ __forceinline__ float tanh_ap(float x) {
    float y;
    asm("tanh.approx.f32 %0, %1;" : "=f"(y) : "f"(x));
    return y;
}
__device__ __forceinline__ float sig_ap(float x) {
    return fmaf(0.5f, tanh_ap(0.5f * x), 0.5f);
}
__device__ __forceinline__ void cp_async4(uint32_t smem_addr, const float* gptr) {
    asm volatile("cp.async.ca.shared.global [%0], [%1], 4;"
                 :: "r"(smem_addr), "l"(gptr));
}
__device__ __forceinline__ void cp_commit() {
    asm volatile("cp.async.commit_group;");
}
__device__ __forceinline__ void cp_wait_ring() {
    asm volatile("cp.async.wait_group %0;" :: "n"(RING - 1));
}

// ---------------------------------------------------------------------------
// K1: GRU layer 1, 3 rows/warp.  x:[B,S,4] -> h1:[B,S,32]
// ---------------------------------------------------------------------------
__global__ __launch_bounds__(128, 3)
void gru_l1_kernel(const float* __restrict__ x,
                   const float* __restrict__ Wih,   // [96,4]
                   const float* __restrict__ Whh,   // [96,32]
                   const float* __restrict__ bih,   // [96]
                   const float* __restrict__ bhh)   // [96]
{
    __shared__ __align__(16) float hbuf[4][2][3][HID];     // 3 KB
    __shared__ __align__(16) float xring[4][RING][3][4];   // 1.5 KB

    const int warp = (blockIdx.x * blockDim.x + threadIdx.x) >> 5;
    const int wl   = threadIdx.x >> 5;
    const int lane = threadIdx.x & 31;

    const int rb = warp * 3;
    const int r0 = min(rb,     B_ROWS - 1);
    const int r1 = min(rb + 1, B_ROWS - 1);
    const int r2 = min(rb + 2, B_ROWS - 1);

    ull whr[16], whz[16], whn[16];
    {
        const ull* pr = reinterpret_cast<const ull*>(Whh + (lane)      * HID);
        const ull* pz = reinterpret_cast<const ull*>(Whh + (32 + lane) * HID);
        const ull* pn = reinterpret_cast<const ull*>(Whh + (64 + lane) * HID);
#pragma unroll
        for (int k = 0; k < 16; k++) { whr[k] = pr[k]; whz[k] = pz[k]; whn[k] = pn[k]; }
    }
    const float4 wir = reinterpret_cast<const float4*>(Wih)[lane];
    const float4 wiz = reinterpret_cast<const float4*>(Wih)[32 + lane];
    const float4 win = reinterpret_cast<const float4*>(Wih)[64 + lane];

    const float br  = bih[lane]      + bhh[lane];
    const float bz  = bih[32 + lane] + bhh[32 + lane];
    const float bin = bih[64 + lane];
    const float bhn = bhh[64 + lane];

    float* op0 = g_h1 + (size_t)r0 * SEQ * HID + lane;
    float* op1 = g_h1 + (size_t)r1 * SEQ * HID + lane;
    float* op2 = g_h1 + (size_t)r2 * SEQ * HID + lane;

    const uint32_t ring_base =
        (uint32_t)__cvta_generic_to_shared(&xring[wl][0][0][0]);

    // lanes 0..11 feed the ring: lane = row*4 + word
    const bool ld_act = lane < 12;
    const int  lr     = min(rb + (lane >> 2), B_ROWS - 1);
    const float* xg_lane = x + (size_t)lr * SEQ * 4 + (lane & 3);

#pragma unroll
    for (int d = 0; d < RING; d++) {
        if (ld_act) cp_async4(ring_base + d * 48 + lane * 4, xg_lane + d * 4);
        cp_commit();
    }

    float h0 = 0.0f, h1v = 0.0f, h2 = 0.0f;
#pragma unroll 1
    for (int s = 0; s < SEQ; s++) {
        hbuf[wl][s & 1][0][lane] = h0;
        hbuf[wl][s & 1][1][lane] = h1v;
        hbuf[wl][s & 1][2][lane] = h2;
        cp_wait_ring();
        __syncwarp();

        const float4 xv0 = *reinterpret_cast<const float4*>(&xring[wl][s & (RING - 1)][0][0]);
        const float4 xv1 = *reinterpret_cast<const float4*>(&xring[wl][s & (RING - 1)][1][0]);
        const float4 xv2 = *reinterpret_cast<const float4*>(&xring[wl][s & (RING - 1)][2][0]);
        const ulonglong2* hp0 = reinterpret_cast<const ulonglong2*>(&hbuf[wl][s & 1][0][0]);
        const ulonglong2* hp1 = reinterpret_cast<const ulonglong2*>(&hbuf[wl][s & 1][1][0]);
        const ulonglong2* hp2 = reinterpret_cast<const ulonglong2*>(&hbuf[wl][s & 1][2][0]);

        if (ld_act && s + RING < SEQ)
            cp_async4(ring_base + ((s + RING) & (RING - 1)) * 48 + lane * 4,
                      xg_lane + (s + RING) * 4);
        cp_commit();

        float ar0 = br, az0 = bz, xn0 = bin;
        float ar1 = br, az1 = bz, xn1 = bin;
        float ar2 = br, az2 = bz, xn2 = bin;
        ar0 = fmaf(wir.x, xv0.x, ar0); ar0 = fmaf(wir.y, xv0.y, ar0);
        ar0 = fmaf(wir.z, xv0.z, ar0); ar0 = fmaf(wir.w, xv0.w, ar0);
        az0 = fmaf(wiz.x, xv0.x, az0); az0 = fmaf(wiz.y, xv0.y, az0);
        az0 = fmaf(wiz.z, xv0.z, az0); az0 = fmaf(wiz.w, xv0.w, az0);
        xn0 = fmaf(win.x, xv0.x, xn0); xn0 = fmaf(win.y, xv0.y, xn0);
        xn0 = fmaf(win.z, xv0.z, xn0); xn0 = fmaf(win.w, xv0.w, xn0);
        ar1 = fmaf(wir.x, xv1.x, ar1); ar1 = fmaf(wir.y, xv1.y, ar1);
        ar1 = fmaf(wir.z, xv1.z, ar1); ar1 = fmaf(wir.w, xv1.w, ar1);
        az1 = fmaf(wiz.x, xv1.x, az1); az1 = fmaf(wiz.y, xv1.y, az1);
        az1 = fmaf(wiz.z, xv1.z, az1); az1 = fmaf(wiz.w, xv1.w, az1);
        xn1 = fmaf(win.x, xv1.x, xn1); xn1 = fmaf(win.y, xv1.y, xn1);
        xn1 = fmaf(win.z, xv1.z, xn1); xn1 = fmaf(win.w, xv1.w, xn1);
        ar2 = fmaf(wir.x, xv2.x, ar2); ar2 = fmaf(wir.y, xv2.y, ar2);
        ar2 = fmaf(wir.z, xv2.z, ar2); ar2 = fmaf(wir.w, xv2.w, ar2);
        az2 = fmaf(wiz.x, xv2.x, az2); az2 = fmaf(wiz.y, xv2.y, az2);
        az2 = fmaf(wiz.z, xv2.z, az2); az2 = fmaf(wiz.w, xv2.w, az2);
        xn2 = fmaf(win.x, xv2.x, xn2); xn2 = fmaf(win.y, xv2.y, xn2);
        xn2 = fmaf(win.z, xv2.z, xn2); xn2 = fmaf(win.w, xv2.w, xn2);

        ull ra0 = 0ull, za0 = 0ull, na0 = 0ull;
        ull ra1 = 0ull, za1 = 0ull, na1 = 0ull;
        ull ra2 = 0ull, za2 = 0ull, na2 = 0ull;
#pragma unroll
        for (int k = 0; k < 8; k++) {
            const ulonglong2 hv0 = hp0[k];
            const ulonglong2 hv1 = hp1[k];
            const ulonglong2 hv2 = hp2[k];
            ra0 = ffma2(whr[2 * k],     hv0.x, ra0);
            za0 = ffma2(whz[2 * k],     hv0.x, za0);
            na0 = ffma2(whn[2 * k],     hv0.x, na0);
            ra1 = ffma2(whr[2 * k],     hv1.x, ra1);
            za1 = ffma2(whz[2 * k],     hv1.x, za1);
            na1 = ffma2(whn[2 * k],     hv1.x, na1);
            ra2 = ffma2(whr[2 * k],     hv2.x, ra2);
            za2 = ffma2(whz[2 * k],     hv2.x, za2);
            na2 = ffma2(whn[2 * k],     hv2.x, na2);
            ra0 = ffma2(whr[2 * k + 1], hv0.y, ra0);
            za0 = ffma2(whz[2 * k + 1], hv0.y, za0);
            na0 = ffma2(whn[2 * k + 1], hv0.y, na0);
            ra1 = ffma2(whr[2 * k + 1], hv1.y, ra1);
            za1 = ffma2(whz[2 * k + 1], hv1.y, za1);
            na1 = ffma2(whn[2 * k + 1], hv1.y, na1);
            ra2 = ffma2(whr[2 * k + 1], hv2.y, ra2);
            za2 = ffma2(whz[2 * k + 1], hv2.y, za2);
            na2 = ffma2(whn[2 * k + 1], hv2.y, na2);
        }
        ar0 += hsum2(ra0);  az0 += hsum2(za0);
        ar1 += hsum2(ra1);  az1 += hsum2(za1);
        ar2 += hsum2(ra2);  az2 += hsum2(za2);
        const float hn0 = bhn + hsum2(na0);
        const float hn1 = bhn + hsum2(na1);
        const float hn2 = bhn + hsum2(na2);

        const float rr0 = sig_ap(ar0);
        const float zz0 = sig_ap(az0);
        const float nn0 = tanh_ap(fmaf(rr0, hn0, xn0));
        h0 = fmaf(zz0, h0 - nn0, nn0);
        const float rr1 = sig_ap(ar1);
        const float zz1 = sig_ap(az1);
        const float nn1 = tanh_ap(fmaf(rr1, hn1, xn1));
        h1v = fmaf(zz1, h1v - nn1, nn1);
        const float rr2 = sig_ap(ar2);
        const float zz2 = sig_ap(az2);
        const float nn2 = tanh_ap(fmaf(rr2, hn2, xn2));
        h2 = fmaf(zz2, h2 - nn2, nn2);

        op0[(size_t)s * HID] = h0;
        op1[(size_t)s * HID] = h1v;
        op2[(size_t)s * HID] = h2;
    }
}

// ---------------------------------------------------------------------------
// K2: xg GEMM, pipelined.  Each warp: one (row, 128-step quarter).
//     xg[r,s,:] = W_ih1 . h1[r,s,:] + b_ih1 (+ b_hh1 folded for r,z gates)
// ---------------------------------------------------------------------------
__global__ __launch_bounds__(128, 3)
void xg_gemm_kernel(const float* __restrict__ Wih,   // [96,32]
                    const float* __restrict__ bih,   // [96]
                    const float* __restrict__ bhh)   // [96]
{
    __shared__ __align__(16) float hring[4][RING][HID];   // 4 KB

    const int task = (blockIdx.x * blockDim.x + threadIdx.x) >> 5;  // 0..16383
    const int wl   = threadIdx.x >> 5;
    const int lane = threadIdx.x & 31;
    const int row  = task >> 2;
    const int q    = task & 3;

    ull wxr[16], wxz[16], wxn[16];
    {
        const ull* p0 = reinterpret_cast<const ull*>(Wih + (lane)      * HID);
        const ull* p1 = reinterpret_cast<const ull*>(Wih + (32 + lane) * HID);
        const ull* p2 = reinterpret_cast<const ull*>(Wih + (64 + lane) * HID);
#pragma unroll
        for (int k = 0; k < 16; k++) { wxr[k] = p0[k]; wxz[k] = p1[k]; wxn[k] = p2[k]; }
    }
    const float gxr = bih[lane]      + bhh[lane];
    const float gxz = bih[32 + lane] + bhh[32 + lane];
    const float gxn = bih[64 + lane];

    const float* hsrc = g_h1 + (size_t)row * SEQ * HID + (size_t)q * 128 * HID;
    float*       xo   = g_xg + (size_t)row * SEQ * 96  + (size_t)q * 128 * 96;

    const uint32_t ring_base =
        (uint32_t)__cvta_generic_to_shared(&hring[wl][0][0]);

#pragma unroll
    for (int d = 0; d < RING; d++) {
        cp_async4(ring_base + d * 128 + lane * 4, hsrc + d * HID + lane);
        cp_commit();
    }

#pragma unroll 1
    for (int s = 0; s < 128; s++) {
        cp_wait_ring();
        __syncwarp();
        const ulonglong2* hp =
            reinterpret_cast<const ulonglong2*>(&hring[wl][s & (RING - 1)][0]);

        if (s + RING < 128)
            cp_async4(ring_base + ((s + RING) & (RING - 1)) * 128 + lane * 4,
                      hsrc + (s + RING) * HID + lane);
        cp_commit();

        ull qr = 0ull, qz = 0ull, qn = 0ull;
#pragma unroll
        for (int k = 0; k < 8; k++) {
            const ulonglong2 hv = hp[k];
            qr = ffma2(wxr[2 * k],     hv.x, qr);
            qz = ffma2(wxz[2 * k],     hv.x, qz);
            qn = ffma2(wxn[2 * k],     hv.x, qn);
            qr = ffma2(wxr[2 * k + 1], hv.y, qr);
            qz = ffma2(wxz[2 * k + 1], hv.y, qz);
            qn = ffma2(wxn[2 * k + 1], hv.y, qn);
        }
        float* o = xo + s * 96;
        o[lane]      = gxr + hsum2(qr);
        o[32 + lane] = gxz + hsum2(qz);
        o[64 + lane] = gxn + hsum2(qn);
    }
}

// ---------------------------------------------------------------------------
// K3: slim layer-2 recurrence + FC, 3 rows/warp.  xg:[B,S,96] -> out:[B]
// ---------------------------------------------------------------------------
__global__ __launch_bounds__(128, 3)
void gru_l2_kernel(const float* __restrict__ Whh,   // [96,32]
                   const float* __restrict__ bhh,   // [96]
                   const float* __restrict__ Wfc2,  // [32,32]
                   const float* __restrict__ bfc2,  // [32]
                   const float* __restrict__ Wfc,   // [1,32]
                   const float* __restrict__ bfc,   // [1]
                   float* __restrict__ out)
{
    __shared__ __align__(16) float hbuf[4][2][3][HID];       // 3 KB
    __shared__ __align__(16) float xring[4][RING][3][96];    // 36.9 KB

    const int warp = (blockIdx.x * blockDim.x + threadIdx.x) >> 5;
    const int wl   = threadIdx.x >> 5;
    const int lane = threadIdx.x & 31;

    const int rb = warp * 3;
    const int r0 = min(rb,     B_ROWS - 1);
    const int r1 = min(rb + 1, B_ROWS - 1);
    const int r2 = min(rb + 2, B_ROWS - 1);

    ull whr[16], whz[16], whn[16];
    {
        const ull* p3 = reinterpret_cast<const ull*>(Whh + (lane)      * HID);
        const ull* p4 = reinterpret_cast<const ull*>(Whh + (32 + lane) * HID);
        const ull* p5 = reinterpret_cast<const ull*>(Whh + (64 + lane) * HID);
#pragma unroll
        for (int k = 0; k < 16; k++) { whr[k] = p3[k]; whz[k] = p4[k]; whn[k] = p5[k]; }
    }
    const float bhn = bhh[64 + lane];

    const float* xsA = g_xg + (size_t)r0 * SEQ * 96;
    const float* xsB = g_xg + (size_t)r1 * SEQ * 96;
    const float* xsC = g_xg + (size_t)r2 * SEQ * 96;

    const uint32_t ring_base =
        (uint32_t)__cvta_generic_to_shared(&xring[wl][0][0][0]);

    // ring slot = 1152 B: [row][gate*32+unit]; 9 cp.async4 per lane per step
#pragma unroll
    for (int d = 0; d < RING; d++) {
        const uint32_t rbse = ring_base + d * 1152;
        cp_async4(rbse +        lane * 4, xsA + d * 96 +      lane);
        cp_async4(rbse + 128  + lane * 4, xsA + d * 96 + 32 + lane);
        cp_async4(rbse + 256  + lane * 4, xsA + d * 96 + 64 + lane);
        cp_async4(rbse + 384  + lane * 4, xsB + d * 96 +      lane);
        cp_async4(rbse + 512  + lane * 4, xsB + d * 96 + 32 + lane);
        cp_async4(rbse + 640  + lane * 4, xsB + d * 96 + 64 + lane);
        cp_async4(rbse + 768  + lane * 4, xsC + d * 96 +      lane);
        cp_async4(rbse + 896  + lane * 4, xsC + d * 96 + 32 + lane);
        cp_async4(rbse + 1024 + lane * 4, xsC + d * 96 + 64 + lane);
        cp_commit();
    }

    float h0 = 0.0f, h1v = 0.0f, h2 = 0.0f;
#pragma unroll 1
    for (int s = 0; s < SEQ; s++) {
        hbuf[wl][s & 1][0][lane] = h0;
        hbuf[wl][s & 1][1][lane] = h1v;
        hbuf[wl][s & 1][2][lane] = h2;
        cp_wait_ring();
        __syncwarp();

        const float* xrow = &xring[wl][s & (RING - 1)][0][0];
        const float xr0 = xrow[lane];
        const float xz0 = xrow[32 + lane];
        const float xn0 = xrow[64 + lane];
        const float xr1 = xrow[96 + lane];
        const float xz1 = xrow[128 + lane];
        const float xn1 = xrow[160 + lane];
        const float xr2 = xrow[192 + lane];
        const float xz2 = xrow[224 + lane];
        const float xn2 = xrow[256 + lane];
        const ulonglong2* hp0 = reinterpret_cast<const ulonglong2*>(&hbuf[wl][s & 1][0][0]);
        const ulonglong2* hp1 = reinterpret_cast<const ulonglong2*>(&hbuf[wl][s & 1][1][0]);
        const ulonglong2* hp2 = reinterpret_cast<const ulonglong2*>(&hbuf[wl][s & 1][2][0]);

        if (s + RING < SEQ) {
            const uint32_t rbse = ring_base + ((s + RING) & (RING - 1)) * 1152;
            const float* gA = xsA + (s + RING) * 96;
            const float* gB = xsB + (s + RING) * 96;
            const float* gC = xsC + (s + RING) * 96;
            cp_async4(rbse +        lane * 4, gA +      lane);
            cp_async4(rbse + 128  + lane * 4, gA + 32 + lane);
            cp_async4(rbse + 256  + lane * 4, gA + 64 + lane);
            cp_async4(rbse + 384  + lane * 4, gB +      lane);
            cp_async4(rbse + 512  + lane * 4, gB + 32 + lane);
            cp_async4(rbse + 640  + lane * 4, gB + 64 + lane);
            cp_async4(rbse + 768  + lane * 4, gC +      lane);
            cp_async4(rbse + 896  + lane * 4, gC + 32 + lane);
            cp_async4(rbse + 1024 + lane * 4, gC + 64 + lane);
        }
        cp_commit();

        ull r0a = 0ull, z0a = 0ull, n0a = 0ull;
        ull r1a = 0ull, z1a = 0ull, n1a = 0ull;
        ull r2a = 0ull, z2a = 0ull, n2a = 0ull;
#pragma unroll
        for (int k = 0; k < 8; k++) {
            const ulonglong2 hv0 = hp0[k];
            const ulonglong2 hv1 = hp1[k];
            const ulonglong2 hv2 = hp2[k];
            r0a = ffma2(whr[2 * k],     hv0.x, r0a);
            z0a = ffma2(whz[2 * k],     hv0.x, z0a);
            n0a = ffma2(whn[2 * k],     hv0.x, n0a);
            r1a = ffma2(whr[2 * k],     hv1.x, r1a);
            z1a = ffma2(whz[2 * k],     hv1.x, z1a);
            n1a = ffma2(whn[2 * k],     hv1.x, n1a);
            r2a = ffma2(whr[2 * k],     hv2.x, r2a);
            z2a = ffma2(whz[2 * k],     hv2.x, z2a);
            n2a = ffma2(whn[2 * k],     hv2.x, n2a);
            r0a = ffma2(whr[2 * k + 1], hv0.y, r0a);
            z0a = ffma2(whz[2 * k + 1], hv0.y, z0a);
            n0a = ffma2(whn[2 * k + 1], hv0.y, n0a);
            r1a = ffma2(whr[2 * k + 1], hv1.y, r1a);
            z1a = ffma2(whz[2 * k + 1], hv1.y, z1a);
            n1a = ffma2(whn[2 * k + 1], hv1.y, n1a);
            r2a = ffma2(whr[2 * k + 1], hv2.y, r2a);
            z2a = ffma2(whz[2 * k + 1], hv2.y, z2a);
            n2a = ffma2(whn[2 * k + 1], hv2.y, n2a);
        }
        const float ar0 = xr0 + hsum2(r0a);
        const float az0 = xz0 + hsum2(z0a);
        const float hn0 = bhn + hsum2(n0a);
        const float ar1 = xr1 + hsum2(r1a);
        const float az1 = xz1 + hsum2(z1a);
        const float hn1 = bhn + hsum2(n1a);
        const float ar2 = xr2 + hsum2(r2a);
        const float az2 = xz2 + hsum2(z2a);
        const float hn2 = bhn + hsum2(n2a);

        const float rr0 = sig_ap(ar0);
        const float zz0 = sig_ap(az0);
        const float nn0 = tanh_ap(fmaf(rr0, hn0, xn0));
        h0 = fmaf(zz0, h0 - nn0, nn0);
        const float rr1 = sig_ap(ar1);
        const float zz1 = sig_ap(az1);
        const float nn1 = tanh_ap(fmaf(rr1, hn1, xn1));
        h1v = fmaf(zz1, h1v - nn1, nn1);
        const float rr2 = sig_ap(ar2);
        const float zz2 = sig_ap(az2);
        const float nn2 = tanh_ap(fmaf(rr2, hn2, xn2));
        h2 = fmaf(zz2, h2 - nn2, nn2);
    }

    // FC2 + FC epilogue for the 3 rows
    {
        hbuf[wl][0][0][lane] = h0;
        hbuf[wl][0][1][lane] = h1v;
        hbuf[wl][0][2][lane] = h2;
        __syncwarp();
        const ulonglong2* hp0 = reinterpret_cast<const ulonglong2*>(&hbuf[wl][0][0][0]);
        const ulonglong2* hp1 = reinterpret_cast<const ulonglong2*>(&hbuf[wl][0][1][0]);
        const ulonglong2* hp2 = reinterpret_cast<const ulonglong2*>(&hbuf[wl][0][2][0]);
        const ull* wf = reinterpret_cast<const ull*>(Wfc2 + lane * HID);
        ull a0 = 0ull, a1 = 0ull, a2 = 0ull;
#pragma unroll
        for (int k = 0; k < 8; k++) {
            const ulonglong2 hv0 = hp0[k];
            const ulonglong2 hv1 = hp1[k];
            const ulonglong2 hv2 = hp2[k];
            a0 = ffma2(wf[2 * k],     hv0.x, a0);
            a1 = ffma2(wf[2 * k],     hv1.x, a1);
            a2 = ffma2(wf[2 * k],     hv2.x, a2);
            a0 = ffma2(wf[2 * k + 1], hv0.y, a0);
            a1 = ffma2(wf[2 * k + 1], hv1.y, a1);
            a2 = ffma2(wf[2 * k + 1], hv2.y, a2);
        }
        const float bf2 = __ldg(bfc2 + lane);
        const float o0 = bf2 + hsum2(a0);
        const float o1 = bf2 + hsum2(a1);
        const float o2 = bf2 + hsum2(a2);

        const float wfc = __ldg(Wfc + lane);
        float p0 = wfc * o0;
        float p1 = wfc * o1;
        float p2 = wfc * o2;
#pragma unroll
        for (int off = 16; off > 0; off >>= 1) {
            p0 += __shfl_xor_sync(0xffffffffu, p0, off);
            p1 += __shfl_xor_sync(0xffffffffu, p1, off);
            p2 += __shfl_xor_sync(0xffffffffu, p2, off);
        }
        if (lane == 0) {
            const float bb = __ldg(bfc);
            out[r0] = p0 + bb;
            out[r1] = p1 + bb;
            out[r2] = p2 + bb;
        }
    }
}

// ---------------------------------------------------------------------------
// Launch
// ---------------------------------------------------------------------------
extern "C" void kernel_launch(void* const* d_in, const int* in_sizes, int n_in,
                              void* d_out, int out_size)
{
    const float* x     = (const float*)d_in[0];
    const float* Wih0  = (const float*)d_in[1];
    const float* Whh0  = (const float*)d_in[2];
    const float* bih0  = (const float*)d_in[3];
    const float* bhh0  = (const float*)d_in[4];
    const float* Wih1  = (const float*)d_in[5];
    const float* Whh1  = (const float*)d_in[6];
    const float* bih1  = (const float*)d_in[7];
    const float* bhh1  = (const float*)d_in[8];
    const float* Wfc2  = (const float*)d_in[9];
    const float* bfc2  = (const float*)d_in[10];
    const float* Wfc   = (const float*)d_in[11];
    const float* bfc   = (const float*)d_in[12];
    float* out = (float*)d_out;

    const int blocks3 = (NW3 + 3) / 4;      // 342 CTAs for 3-row kernels

    gru_l1_kernel<<<blocks3, 128>>>(x, Wih0, Whh0, bih0, bhh0);
    xg_gemm_kernel<<<B_ROWS, 128>>>(Wih1, bih1, bhh1);   // 16384 warp-tasks
    gru_l2_kernel<<<blocks3, 128>>>(Whh1, bhh1, Wfc2, bfc2, Wfc, bfc, out);
}

// round 16
// speedup vs baseline: 1.3650x; 1.2311x over previous
#include <cuda_runtime.h>
#include <cuda_bf16.h>
#include <cstdint>

// ---------------------------------------------------------------------------
// 2-layer GRU (H=32, INPUT=4, B=4096, S=512) + FC(32->32) + FC(32->1)
//
// Pass 1: R11 version (2 rows/warp, 2048 warps, 1.15 waves at 3/SMSP).
// Pass 2: 4 rows/warp -> 1024 warps -> ONE residency wave at 2/SMSP.
//   Full layer-2 (x-side + h-side weights register-resident, 192 regs);
//   per-step k-loop split into (r,z) and (n) passes to halve accumulator
//   register pressure and stay under the 255-reg ceiling.
// ---------------------------------------------------------------------------

#define B_ROWS 4096
#define SEQ    512
#define HID    32
#define RING   8
#define NWARP  (B_ROWS / 2)       // pass-1 warps (2 rows each)
#define NW4    (B_ROWS / 4)       // pass-2 warps (4 rows each) = 1024

typedef unsigned long long ull;

__device__ float g_h1[(size_t)B_ROWS * SEQ * HID];   // 268 MB scratch

__device__ __forceinline__ ull ffma2(ull a, ull b, ull c) {
    ull d;
    asm("fma.rn.f32x2 %0, %1, %2, %3;" : "=l"(d) : "l"(a), "l"(b), "l"(c));
    return d;
}
__device__ __forceinline__ float hsum2(ull v) {
    float2 r;
    asm("mov.b64 {%0, %1}, %2;" : "=f"(r.x), "=f"(r.y) : "l"(v));
    return r.x + r.y;
}
__device__ __forceinline__ float tanh_ap(float x) {
    float y;
    asm("tanh.approx.f32 %0, %1;" : "=f"(y) : "f"(x));
    return y;
}
__device__ __forceinline__ float sig_ap(float x) {
    return fmaf(0.5f, tanh_ap(0.5f * x), 0.5f);
}
__device__ __forceinline__ void cp_async4(uint32_t smem_addr, const float* gptr) {
    asm volatile("cp.async.ca.shared.global [%0], [%1], 4;"
                 :: "r"(smem_addr), "l"(gptr));
}
__device__ __forceinline__ void cp_commit() {
    asm volatile("cp.async.commit_group;");
}
__device__ __forceinline__ void cp_wait_ring() {
    asm volatile("cp.async.wait_group %0;" :: "n"(RING - 1));
}

// ---------------------------------------------------------------------------
// Pass 1: GRU layer 1, 2 rows/warp (R11).  x:[B,S,4] -> h1:[B,S,32]
// ---------------------------------------------------------------------------
__global__ __launch_bounds__(128, 3)
void gru_layer1_kernel(const float* __restrict__ x,
                       const float* __restrict__ Wih,   // [96,4]
                       const float* __restrict__ Whh,   // [96,32]
                       const float* __restrict__ bih,   // [96]
                       const float* __restrict__ bhh)   // [96]
{
    __shared__ __align__(16) float hbuf[4][2][2][HID];
    __shared__ __align__(16) float xring[4][RING][2][4];

    const int warp = (blockIdx.x * blockDim.x + threadIdx.x) >> 5;
    const int wl   = threadIdx.x >> 5;
    const int lane = threadIdx.x & 31;
    if (warp >= NWARP) return;

    ull whr[16], whz[16], whn[16];
    {
        const ull* pr = reinterpret_cast<const ull*>(Whh + (lane)      * HID);
        const ull* pz = reinterpret_cast<const ull*>(Whh + (32 + lane) * HID);
        const ull* pn = reinterpret_cast<const ull*>(Whh + (64 + lane) * HID);
#pragma unroll
        for (int k = 0; k < 16; k++) { whr[k] = pr[k]; whz[k] = pz[k]; whn[k] = pn[k]; }
    }
    const float4 wir = reinterpret_cast<const float4*>(Wih)[lane];
    const float4 wiz = reinterpret_cast<const float4*>(Wih)[32 + lane];
    const float4 win = reinterpret_cast<const float4*>(Wih)[64 + lane];

    const float br  = bih[lane]      + bhh[lane];
    const float bz  = bih[32 + lane] + bhh[32 + lane];
    const float bin = bih[64 + lane];
    const float bhn = bhh[64 + lane];

    const int r0 = warp * 2, r1 = warp * 2 + 1;
    const float* xs0 = x + (size_t)r0 * SEQ * 4;
    const float* xs1 = x + (size_t)r1 * SEQ * 4;
    float* op0 = g_h1 + (size_t)r0 * SEQ * HID + lane;
    float* op1 = g_h1 + (size_t)r1 * SEQ * HID + lane;

    const uint32_t ring_base =
        (uint32_t)__cvta_generic_to_shared(&xring[wl][0][0][0]);

    const bool ld_act = lane < 8;
    const float* xg = (lane < 4) ? (xs0 + lane) : (xs1 + (lane - 4));

#pragma unroll
    for (int d = 0; d < RING; d++) {
        if (ld_act) cp_async4(ring_base + d * 32 + lane * 4, xg + d * 4);
        cp_commit();
    }

    float h0 = 0.0f, h1 = 0.0f;
#pragma unroll 1
    for (int s = 0; s < SEQ; s++) {
        hbuf[wl][s & 1][0][lane] = h0;
        hbuf[wl][s & 1][1][lane] = h1;
        cp_wait_ring();
        __syncwarp();

        const float4 xv0 =
            *reinterpret_cast<const float4*>(&xring[wl][s & (RING - 1)][0][0]);
        const float4 xv1 =
            *reinterpret_cast<const float4*>(&xring[wl][s & (RING - 1)][1][0]);
        const ulonglong2* hp0 =
            reinterpret_cast<const ulonglong2*>(&hbuf[wl][s & 1][0][0]);
        const ulonglong2* hp1 =
            reinterpret_cast<const ulonglong2*>(&hbuf[wl][s & 1][1][0]);

        if (ld_act && s + RING < SEQ)
            cp_async4(ring_base + ((s + RING) & (RING - 1)) * 32 + lane * 4,
                      xg + (s + RING) * 4);
        cp_commit();

        float ar0 = br, az0 = bz, xn0 = bin;
        float ar1 = br, az1 = bz, xn1 = bin;
        ar0 = fmaf(wir.x, xv0.x, ar0); ar0 = fmaf(wir.y, xv0.y, ar0);
        ar0 = fmaf(wir.z, xv0.z, ar0); ar0 = fmaf(wir.w, xv0.w, ar0);
        az0 = fmaf(wiz.x, xv0.x, az0); az0 = fmaf(wiz.y, xv0.y, az0);
        az0 = fmaf(wiz.z, xv0.z, az0); az0 = fmaf(wiz.w, xv0.w, az0);
        xn0 = fmaf(win.x, xv0.x, xn0); xn0 = fmaf(win.y, xv0.y, xn0);
        xn0 = fmaf(win.z, xv0.z, xn0); xn0 = fmaf(win.w, xv0.w, xn0);
        ar1 = fmaf(wir.x, xv1.x, ar1); ar1 = fmaf(wir.y, xv1.y, ar1);
        ar1 = fmaf(wir.z, xv1.z, ar1); ar1 = fmaf(wir.w, xv1.w, ar1);
        az1 = fmaf(wiz.x, xv1.x, az1); az1 = fmaf(wiz.y, xv1.y, az1);
        az1 = fmaf(wiz.z, xv1.z, az1); az1 = fmaf(wiz.w, xv1.w, az1);
        xn1 = fmaf(win.x, xv1.x, xn1); xn1 = fmaf(win.y, xv1.y, xn1);
        xn1 = fmaf(win.z, xv1.z, xn1); xn1 = fmaf(win.w, xv1.w, xn1);

        ull ra0 = 0ull, za0 = 0ull, na0 = 0ull;
        ull ra1 = 0ull, za1 = 0ull, na1 = 0ull;
#pragma unroll
        for (int k = 0; k < 8; k++) {
            const ulonglong2 hv0 = hp0[k];
            const ulonglong2 hv1 = hp1[k];
            ra0 = ffma2(whr[2 * k],     hv0.x, ra0);
            za0 = ffma2(whz[2 * k],     hv0.x, za0);
            na0 = ffma2(whn[2 * k],     hv0.x, na0);
            ra1 = ffma2(whr[2 * k],     hv1.x, ra1);
            za1 = ffma2(whz[2 * k],     hv1.x, za1);
            na1 = ffma2(whn[2 * k],     hv1.x, na1);
            ra0 = ffma2(whr[2 * k + 1], hv0.y, ra0);
            za0 = ffma2(whz[2 * k + 1], hv0.y, za0);
            na0 = ffma2(whn[2 * k + 1], hv0.y, na0);
            ra1 = ffma2(whr[2 * k + 1], hv1.y, ra1);
            za1 = ffma2(whz[2 * k + 1], hv1.y, za1);
            na1 = ffma2(whn[2 * k + 1], hv1.y, na1);
        }
        ar0 += hsum2(ra0);  az0 += hsum2(za0);
        ar1 += hsum2(ra1);  az1 += hsum2(za1);
        const float hn0 = bhn + hsum2(na0);
        const float hn1 = bhn + hsum2(na1);

        const float rr0 = sig_ap(ar0);
        const float zz0 = sig_ap(az0);
        const float nn0 = tanh_ap(fmaf(rr0, hn0, xn0));
        h0 = fmaf(zz0, h0 - nn0, nn0);
        const float rr1 = sig_ap(ar1);
        const float zz1 = sig_ap(az1);
        const float nn1 = tanh_ap(fmaf(rr1, hn1, xn1));
        h1 = fmaf(zz1, h1 - nn1, nn1);

        op0[(size_t)s * HID] = h0;
        op1[(size_t)s * HID] = h1;
    }
}

// ---------------------------------------------------------------------------
// Pass 2: GRU layer 2 + FC, 4 rows/warp (ONE wave).  h1 -> out
// ---------------------------------------------------------------------------
__global__ __launch_bounds__(128, 2)
void gru_layer2_fc_kernel(const float* __restrict__ Wih,   // [96,32]
                          const float* __restrict__ Whh,   // [96,32]
                          const float* __restrict__ bih,   // [96]
                          const float* __restrict__ bhh,   // [96]
                          const float* __restrict__ Wfc2,  // [32,32]
                          const float* __restrict__ bfc2,  // [32]
                          const float* __restrict__ Wfc,   // [1,32]
                          const float* __restrict__ bfc,   // [1]
                          float* __restrict__ out)
{
    __shared__ __align__(16) float hbuf[4][2][4][HID];      // 4 KB
    __shared__ __align__(16) float xring[4][RING][4][HID];  // 16 KB

    const int warp = (blockIdx.x * blockDim.x + threadIdx.x) >> 5;
    const int wl   = threadIdx.x >> 5;
    const int lane = threadIdx.x & 31;
    if (warp >= NW4) return;

    ull wir[16], wiz[16], win[16], whr[16], whz[16], whn[16];
    {
        const ull* p0 = reinterpret_cast<const ull*>(Wih + (lane)      * HID);
        const ull* p1 = reinterpret_cast<const ull*>(Wih + (32 + lane) * HID);
        const ull* p2 = reinterpret_cast<const ull*>(Wih + (64 + lane) * HID);
        const ull* p3 = reinterpret_cast<const ull*>(Whh + (lane)      * HID);
        const ull* p4 = reinterpret_cast<const ull*>(Whh + (32 + lane) * HID);
        const ull* p5 = reinterpret_cast<const ull*>(Whh + (64 + lane) * HID);
#pragma unroll
        for (int k = 0; k < 16; k++) {
            wir[k] = p0[k]; wiz[k] = p1[k]; win[k] = p2[k];
            whr[k] = p3[k]; whz[k] = p4[k]; whn[k] = p5[k];
        }
    }
    const float br  = bih[lane]      + bhh[lane];
    const float bz  = bih[32 + lane] + bhh[32 + lane];
    const float bin = bih[64 + lane];
    const float bhn = bhh[64 + lane];

    const float* xs0 = g_h1 + (size_t)(warp * 4)     * SEQ * HID;
    const float* xs1 = g_h1 + (size_t)(warp * 4 + 1) * SEQ * HID;
    const float* xs2 = g_h1 + (size_t)(warp * 4 + 2) * SEQ * HID;
    const float* xs3 = g_h1 + (size_t)(warp * 4 + 3) * SEQ * HID;

    const uint32_t ring_base =
        (uint32_t)__cvta_generic_to_shared(&xring[wl][0][0][0]);

    // slot = 512 B (4 rows x 128 B); 4 cp.async4 per lane
#pragma unroll
    for (int d = 0; d < RING; d++) {
        const uint32_t rbs = ring_base + d * 512;
        cp_async4(rbs +       lane * 4, xs0 + d * HID + lane);
        cp_async4(rbs + 128 + lane * 4, xs1 + d * HID + lane);
        cp_async4(rbs + 256 + lane * 4, xs2 + d * HID + lane);
        cp_async4(rbs + 384 + lane * 4, xs3 + d * HID + lane);
        cp_commit();
    }

    float h0 = 0.0f, h1 = 0.0f, h2 = 0.0f, h3 = 0.0f;
#pragma unroll 1
    for (int s = 0; s < SEQ; s++) {
        hbuf[wl][s & 1][0][lane] = h0;
        hbuf[wl][s & 1][1][lane] = h1;
        hbuf[wl][s & 1][2][lane] = h2;
        hbuf[wl][s & 1][3][lane] = h3;
        cp_wait_ring();
        __syncwarp();

        const int slot = s & (RING - 1);
        const ulonglong2* xp0 = reinterpret_cast<const ulonglong2*>(&xring[wl][slot][0][0]);
        const ulonglong2* xp1 = reinterpret_cast<const ulonglong2*>(&xring[wl][slot][1][0]);
        const ulonglong2* xp2 = reinterpret_cast<const ulonglong2*>(&xring[wl][slot][2][0]);
        const ulonglong2* xp3 = reinterpret_cast<const ulonglong2*>(&xring[wl][slot][3][0]);
        const ulonglong2* hp0 = reinterpret_cast<const ulonglong2*>(&hbuf[wl][s & 1][0][0]);
        const ulonglong2* hp1 = reinterpret_cast<const ulonglong2*>(&hbuf[wl][s & 1][1][0]);
        const ulonglong2* hp2 = reinterpret_cast<const ulonglong2*>(&hbuf[wl][s & 1][2][0]);
        const ulonglong2* hp3 = reinterpret_cast<const ulonglong2*>(&hbuf[wl][s & 1][3][0]);

        if (s + RING < SEQ) {
            const uint32_t rbs = ring_base + ((s + RING) & (RING - 1)) * 512;
            cp_async4(rbs +       lane * 4, xs0 + (s + RING) * HID + lane);
            cp_async4(rbs + 128 + lane * 4, xs1 + (s + RING) * HID + lane);
            cp_async4(rbs + 256 + lane * 4, xs2 + (s + RING) * HID + lane);
            cp_async4(rbs + 384 + lane * 4, xs3 + (s + RING) * HID + lane);
        }
        cp_commit();

        // -------- pass 1: r,z gates for 4 rows (8 accumulators) --------
        ull ra0 = 0ull, za0 = 0ull, ra1 = 0ull, za1 = 0ull;
        ull ra2 = 0ull, za2 = 0ull, ra3 = 0ull, za3 = 0ull;
#pragma unroll
        for (int k = 0; k < 8; k++) {
            const ulonglong2 xv0 = xp0[k];
            const ulonglong2 hv0 = hp0[k];
            const ulonglong2 xv1 = xp1[k];
            const ulonglong2 hv1 = hp1[k];
            const ulonglong2 xv2 = xp2[k];
            const ulonglong2 hv2 = hp2[k];
            const ulonglong2 xv3 = xp3[k];
            const ulonglong2 hv3 = hp3[k];
            ra0 = ffma2(wir[2 * k],     xv0.x, ra0);
            za0 = ffma2(wiz[2 * k],     xv0.x, za0);
            ra0 = ffma2(whr[2 * k],     hv0.x, ra0);
            za0 = ffma2(whz[2 * k],     hv0.x, za0);
            ra1 = ffma2(wir[2 * k],     xv1.x, ra1);
            za1 = ffma2(wiz[2 * k],     xv1.x, za1);
            ra1 = ffma2(whr[2 * k],     hv1.x, ra1);
            za1 = ffma2(whz[2 * k],     hv1.x, za1);
            ra2 = ffma2(wir[2 * k],     xv2.x, ra2);
            za2 = ffma2(wiz[2 * k],     xv2.x, za2);
            ra2 = ffma2(whr[2 * k],     hv2.x, ra2);
            za2 = ffma2(whz[2 * k],     hv2.x, za2);
            ra3 = ffma2(wir[2 * k],     xv3.x, ra3);
            za3 = ffma2(wiz[2 * k],     xv3.x, za3);
            ra3 = ffma2(whr[2 * k],     hv3.x, ra3);
            za3 = ffma2(whz[2 * k],     hv3.x, za3);
            ra0 = ffma2(wir[2 * k + 1], xv0.y, ra0);
            za0 = ffma2(wiz[2 * k + 1], xv0.y, za0);
            ra0 = ffma2(whr[2 * k + 1], hv0.y, ra0);
            za0 = ffma2(whz[2 * k + 1], hv0.y, za0);
            ra1 = ffma2(wir[2 * k + 1], xv1.y, ra1);
            za1 = ffma2(wiz[2 * k + 1], xv1.y, za1);
            ra1 = ffma2(whr[2 * k + 1], hv1.y, ra1);
            za1 = ffma2(whz[2 * k + 1], hv1.y, za1);
            ra2 = ffma2(wir[2 * k + 1], xv2.y, ra2);
            za2 = ffma2(wiz[2 * k + 1], xv2.y, za2);
            ra2 = ffma2(whr[2 * k + 1], hv2.y, ra2);
            za2 = ffma2(whz[2 * k + 1], hv2.y, za2);
            ra3 = ffma2(wir[2 * k + 1], xv3.y, ra3);
            za3 = ffma2(wiz[2 * k + 1], xv3.y, za3);
            ra3 = ffma2(whr[2 * k + 1], hv3.y, ra3);
            za3 = ffma2(whz[2 * k + 1], hv3.y, za3);
        }
        const float rr0 = sig_ap(br + hsum2(ra0));
        const float zz0 = sig_ap(bz + hsum2(za0));
        const float rr1 = sig_ap(br + hsum2(ra1));
        const float zz1 = sig_ap(bz + hsum2(za1));
        const float rr2 = sig_ap(br + hsum2(ra2));
        const float zz2 = sig_ap(bz + hsum2(za2));
        const float rr3 = sig_ap(br + hsum2(ra3));
        const float zz3 = sig_ap(bz + hsum2(za3));

        // -------- pass 2: n gates for 4 rows (8 accumulators) --------
        ull xa0 = 0ull, na0 = 0ull, xa1 = 0ull, na1 = 0ull;
        ull xa2 = 0ull, na2 = 0ull, xa3 = 0ull, na3 = 0ull;
#pragma unroll
        for (int k = 0; k < 8; k++) {
            const ulonglong2 xv0 = xp0[k];
            const ulonglong2 hv0 = hp0[k];
            const ulonglong2 xv1 = xp1[k];
            const ulonglong2 hv1 = hp1[k];
            const ulonglong2 xv2 = xp2[k];
            const ulonglong2 hv2 = hp2[k];
            const ulonglong2 xv3 = xp3[k];
            const ulonglong2 hv3 = hp3[k];
            xa0 = ffma2(win[2 * k],     xv0.x, xa0);
            na0 = ffma2(whn[2 * k],     hv0.x, na0);
            xa1 = ffma2(win[2 * k],     xv1.x, xa1);
            na1 = ffma2(whn[2 * k],     hv1.x, na1);
            xa2 = ffma2(win[2 * k],     xv2.x, xa2);
            na2 = ffma2(whn[2 * k],     hv2.x, na2);
            xa3 = ffma2(win[2 * k],     xv3.x, xa3);
            na3 = ffma2(whn[2 * k],     hv3.x, na3);
            xa0 = ffma2(win[2 * k + 1], xv0.y, xa0);
            na0 = ffma2(whn[2 * k + 1], hv0.y, na0);
            xa1 = ffma2(win[2 * k + 1], xv1.y, xa1);
            na1 = ffma2(whn[2 * k + 1], hv1.y, na1);
            xa2 = ffma2(win[2 * k + 1], xv2.y, xa2);
            na2 = ffma2(whn[2 * k + 1], hv2.y, na2);
            xa3 = ffma2(win[2 * k + 1], xv3.y, xa3);
            na3 = ffma2(whn[2 * k + 1], hv3.y, na3);
        }
        const float xn0 = bin + hsum2(xa0);
        const float hn0 = bhn + hsum2(na0);
        const float xn1 = bin + hsum2(xa1);
        const float hn1 = bhn + hsum2(na1);
        const float xn2 = bin + hsum2(xa2);
        const float hn2 = bhn + hsum2(na2);
        const float xn3 = bin + hsum2(xa3);
        const float hn3 = bhn + hsum2(na3);

        const float nn0 = tanh_ap(fmaf(rr0, hn0, xn0));
        h0 = fmaf(zz0, h0 - nn0, nn0);
        const float nn1 = tanh_ap(fmaf(rr1, hn1, xn1));
        h1 = fmaf(zz1, h1 - nn1, nn1);
        const float nn2 = tanh_ap(fmaf(rr2, hn2, xn2));
        h2 = fmaf(zz2, h2 - nn2, nn2);
        const float nn3 = tanh_ap(fmaf(rr3, hn3, xn3));
        h3 = fmaf(zz3, h3 - nn3, nn3);
    }

    // FC2 + FC epilogue for 4 rows
    {
        hbuf[wl][0][0][lane] = h0;
        hbuf[wl][0][1][lane] = h1;
        hbuf[wl][0][2][lane] = h2;
        hbuf[wl][0][3][lane] = h3;
        __syncwarp();
        const ulonglong2* hp0 = reinterpret_cast<const ulonglong2*>(&hbuf[wl][0][0][0]);
        const ulonglong2* hp1 = reinterpret_cast<const ulonglong2*>(&hbuf[wl][0][1][0]);
        const ulonglong2* hp2 = reinterpret_cast<const ulonglong2*>(&hbuf[wl][0][2][0]);
        const ulonglong2* hp3 = reinterpret_cast<const ulonglong2*>(&hbuf[wl][0][3][0]);
        const ull* wf = reinterpret_cast<const ull*>(Wfc2 + lane * HID);
        ull a0 = 0ull, a1 = 0ull, a2 = 0ull, a3 = 0ull;
#pragma unroll
        for (int k = 0; k < 8; k++) {
            const ulonglong2 hv0 = hp0[k];
            const ulonglong2 hv1 = hp1[k];
            const ulonglong2 hv2 = hp2[k];
            const ulonglong2 hv3 = hp3[k];
            a0 = ffma2(wf[2 * k],     hv0.x, a0);
            a1 = ffma2(wf[2 * k],     hv1.x, a1);
            a2 = ffma2(wf[2 * k],     hv2.x, a2);
            a3 = ffma2(wf[2 * k],     hv3.x, a3);
            a0 = ffma2(wf[2 * k + 1], hv0.y, a0);
            a1 = ffma2(wf[2 * k + 1], hv1.y, a1);
            a2 = ffma2(wf[2 * k + 1], hv2.y, a2);
            a3 = ffma2(wf[2 * k + 1], hv3.y, a3);
        }
        const float bf2 = __ldg(bfc2 + lane);
        const float o0 = bf2 + hsum2(a0);
        const float o1 = bf2 + hsum2(a1);
        const float o2 = bf2 + hsum2(a2);
        const float o3 = bf2 + hsum2(a3);

        const float wfc = __ldg(Wfc + lane);
        float p0 = wfc * o0;
        float p1 = wfc * o1;
        float p2 = wfc * o2;
        float p3 = wfc * o3;
#pragma unroll
        for (int off = 16; off > 0; off >>= 1) {
            p0 += __shfl_xor_sync(0xffffffffu, p0, off);
            p1 += __shfl_xor_sync(0xffffffffu, p1, off);
            p2 += __shfl_xor_sync(0xffffffffu, p2, off);
            p3 += __shfl_xor_sync(0xffffffffu, p3, off);
        }
        if (lane == 0) {
            const float bb = __ldg(bfc);
            out[warp * 4]     = p0 + bb;
            out[warp * 4 + 1] = p1 + bb;
            out[warp * 4 + 2] = p2 + bb;
            out[warp * 4 + 3] = p3 + bb;
        }
    }
}

// ---------------------------------------------------------------------------
// Launch
// ---------------------------------------------------------------------------
extern "C" void kernel_launch(void* const* d_in, const int* in_sizes, int n_in,
                              void* d_out, int out_size)
{
    const float* x     = (const float*)d_in[0];
    const float* Wih0  = (const float*)d_in[1];
    const float* Whh0  = (const float*)d_in[2];
    const float* bih0  = (const float*)d_in[3];
    const float* bhh0  = (const float*)d_in[4];
    const float* Wih1  = (const float*)d_in[5];
    const float* Whh1  = (const float*)d_in[6];
    const float* bih1  = (const float*)d_in[7];
    const float* bhh1  = (const float*)d_in[8];
    const float* Wfc2  = (const float*)d_in[9];
    const float* bfc2  = (const float*)d_in[10];
    const float* Wfc   = (const float*)d_in[11];
    const float* bfc   = (const float*)d_in[12];
    float* out = (float*)d_out;

    gru_layer1_kernel<<<NWARP / 4, 128>>>(x, Wih0, Whh0, bih0, bhh0);
    gru_layer2_fc_kernel<<<NW4 / 4, 128>>>(Wih1, Whh1, bih1, bhh1,
                                           Wfc2, bfc2, Wfc, bfc, out);
}